// round 14
// baseline (speedup 1.0000x reference)
#include <cuda_runtime.h>
#include <math.h>

// Problem constants (fixed by the reference setup)
#define Bd   128
#define Vd   4
#define Dd   128
#define Nd   512           // B*V
#define ANCH 4             // anchors per block
#define GRID (Nd / ANCH)   // 128 blocks
#define NT   512           // threads per block
#define NW   16            // warps
#define WR   16            // rows per warp per tile
#define TILE 256           // rows per tile
#define RS   136           // padded row stride; mid-row pad at 68 (conflict-free)
#define MID  68            // k-half 1 starts at float 68 within a row
#define PMAX 64            // max positives per anchor (padded)
#define WROWS 24           // buf0 (16) + buf1 (8) rows per warp

#define SM_ROWS (NW * WROWS * RS)   // 1.5-buffered warp-private row buffers
#define SM_SA   (ANCH * RS)         // anchor rows (same padded layout)
#define SM_SDM  (ANCH * Nd)
#define DYN_BYTES ((SM_ROWS + SM_SA + SM_SDM) * 4)   // ~219 KB, fits 227 KB cap

#define INF_F __int_as_float(0x7f800000)

// Scratch (device globals — no allocation allowed)
__device__ float        g_part[GRID];
__device__ unsigned int g_cntp[GRID];
__device__ unsigned int g_done = 0;

// packed fp32x2 helpers
__device__ __forceinline__ void fma2(unsigned long long& acc,
                                     unsigned long long a,
                                     unsigned long long b) {
    asm("fma.rn.f32x2 %0, %1, %2, %0;" : "+l"(acc) : "l"(a), "l"(b));
}
__device__ __forceinline__ float sum2(unsigned long long v) {
    float lo, hi;
    asm("mov.b64 {%0,%1}, %2;" : "=f"(lo), "=f"(hi) : "l"(v));
    return lo + hi;
}

// cp.async helpers (16B)
__device__ __forceinline__ void cp16(unsigned dst, const void* src) {
    asm volatile("cp.async.cg.shared.global [%0], [%1], 16;" :: "r"(dst), "l"(src));
}
#define CP_COMMIT() asm volatile("cp.async.commit_group;")
#define CP_WAIT1()  asm volatile("cp.async.wait_group 1;" ::: "memory")
#define CP_WAIT0()  asm volatile("cp.async.wait_group 0;" ::: "memory")

// padded store index for float d within a row (halves at 0 and MID)
static __device__ __forceinline__ int pidx(int d) {
    return (d & 63) + (d >> 6) * MID;
}

__global__ void __launch_bounds__(NT, 1)
fused_triplet_kernel(const float* __restrict__ feat,
                     const int*   __restrict__ labels,
                     float*       __restrict__ out) {
    extern __shared__ float smem[];
    float* rows = smem;                 // NW * WROWS * RS
    float* sa   = rows + SM_ROWS;       // ANCH * RS
    float* sdm  = sa + SM_SA;           // ANCH * Nd

    __shared__ int          slab[Nd];
    __shared__ float        spp[ANCH][PMAX];
    __shared__ float        srt[ANCH][PMAX];
    __shared__ float        sfx[ANCH][PMAX];
    __shared__ int          snpos[ANCH];
    __shared__ float        s_invna[ANCH];
    __shared__ float        swsum[NW];
    __shared__ unsigned int swcnt[NW];
    __shared__ int          sIsLast;

    const int t    = threadIdx.x;
    const int w    = t >> 5;
    const int lane = t & 31;
    const int blk  = blockIdx.x;

    // row n of emb <- features[n & 127, n >> 7, :]
    auto row_ptr = [&](int n) -> const float* {
        return feat + (size_t)(n & (Bd - 1)) * (Vd * Dd) + (n >> 7) * Dd;
    };

    float* wbuf0 = rows + w * (WROWS * RS);   // 16-row buffer (tile 0 / tile1-hi)
    float* wbuf1 = wbuf0 + WR * RS;           // 8-row buffer (tile1-lo)

    const unsigned db0 = (unsigned)__cvta_generic_to_shared(wbuf0);
    const unsigned db1 = (unsigned)__cvta_generic_to_shared(wbuf1);
    const unsigned lo  = (unsigned)pidx(lane * 4) * 4;   // padded lane offset (bytes)

    // ---- g0: tile 0 (16 rows -> buf0);  g1: tile1 rows 0-7 -> buf1 ----
#pragma unroll
    for (int rr = 0; rr < WR; rr++)
        cp16(db0 + rr * (RS * 4) + lo, row_ptr(w * WR + rr) + lane * 4);
    CP_COMMIT();
#pragma unroll
    for (int rr = 0; rr < 8; rr++)
        cp16(db1 + rr * (RS * 4) + lo, row_ptr(TILE + w * WR + rr) + lane * 4);
    CP_COMMIT();

    // ---- anchors into shared (padded layout) + labels (plain stores) ----
    slab[t] = labels[t & (Bd - 1)];
    if (t < ANCH * Dd) {
        int i = t >> 7;
        int d = t & (Dd - 1);
        sa[i * RS + pidx(d)] = row_ptr(blk * ANCH + i)[d];
    }
    if (t < ANCH) snpos[t] = 0;
    if (t < ANCH * PMAX) srt[t >> 6][t & 63] = INF_F;
    __syncthreads();   // sa + slab visible

    // anchor inverse norms (warps 0..3 read padded sa)
    if (w < ANCH) {
        float4 v = *reinterpret_cast<const float4*>(
            sa + w * RS + (lane & 15) * 4 + (lane >> 4) * MID);
        float s = v.x * v.x + v.y * v.y + v.z * v.z + v.w * v.w;
#pragma unroll
        for (int o = 16; o > 0; o >>= 1) s += __shfl_xor_sync(0xffffffffu, s, o);
        if (lane == 0) s_invna[w] = rsqrtf(s);
    }
    __syncthreads();   // s_invna visible

    const int kh = lane & 1;    // k-half (partner = lane^1)
    const int rl = lane >> 1;   // row within warp's 16

    const ulonglong2* a0p = reinterpret_cast<const ulonglong2*>(sa + 0 * RS + kh * MID);
    const ulonglong2* a1p = reinterpret_cast<const ulonglong2*>(sa + 1 * RS + kh * MID);
    const ulonglong2* a2p = reinterpret_cast<const ulonglong2*>(sa + 2 * RS + kh * MID);
    const ulonglong2* a3p = reinterpret_cast<const ulonglong2*>(sa + 3 * RS + kh * MID);

    const float ina0 = s_invna[0];
    const float ina1 = s_invna[1];
    const float ina2 = s_invna[2];
    const float ina3 = s_invna[3];

    // ---- compute a 16-row tile slice from rowp (combine halves via shfl^1) ----
    auto compute_tile = [&](const ulonglong2* rowp, int gbase) {
        unsigned long long c0a=0,c0b=0,c1a=0,c1b=0,c2a=0,c2b=0,
                           c3a=0,c3b=0,c4a=0,c4b=0;
#pragma unroll
        for (int c = 0; c < 16; c++) {
            ulonglong2 f  = rowp[c];
            ulonglong2 a0 = a0p[c];
            ulonglong2 a1 = a1p[c];
            ulonglong2 a2 = a2p[c];
            ulonglong2 a3 = a3p[c];
            fma2(c0a, f.x, a0.x);  fma2(c0b, f.y, a0.y);
            fma2(c1a, f.x, a1.x);  fma2(c1b, f.y, a1.y);
            fma2(c2a, f.x, a2.x);  fma2(c2b, f.y, a2.y);
            fma2(c3a, f.x, a3.x);  fma2(c3b, f.y, a3.y);
            fma2(c4a, f.x, f.x);   fma2(c4b, f.y, f.y);
        }
        float d0 = sum2(c0a) + sum2(c0b);
        float d1 = sum2(c1a) + sum2(c1b);
        float d2 = sum2(c2a) + sum2(c2b);
        float d3 = sum2(c3a) + sum2(c3b);
        float sq = sum2(c4a) + sum2(c4b);
        d0 += __shfl_xor_sync(0xffffffffu, d0, 1);
        d1 += __shfl_xor_sync(0xffffffffu, d1, 1);
        d2 += __shfl_xor_sync(0xffffffffu, d2, 1);
        d3 += __shfl_xor_sync(0xffffffffu, d3, 1);
        sq += __shfl_xor_sync(0xffffffffu, sq, 1);

        float invnj = rsqrtf(sq);
        int gj = gbase + rl;
        if (kh == 0) {
            float s0 = fmaxf(2.f - 2.f * (d0 * ina0 * invnj), 0.f);
            float s1 = fmaxf(2.f - 2.f * (d1 * ina1 * invnj), 0.f);
            sdm[0 * Nd + gj] = (s0 > 0.f) ? s0 * rsqrtf(s0) : 0.f;
            sdm[1 * Nd + gj] = (s1 > 0.f) ? s1 * rsqrtf(s1) : 0.f;
        } else {
            float s2 = fmaxf(2.f - 2.f * (d2 * ina2 * invnj), 0.f);
            float s3 = fmaxf(2.f - 2.f * (d3 * ina3 * invnj), 0.f);
            sdm[2 * Nd + gj] = (s2 > 0.f) ? s2 * rsqrtf(s2) : 0.f;
            sdm[3 * Nd + gj] = (s3 > 0.f) ? s3 * rsqrtf(s3) : 0.f;
        }
    };

    CP_WAIT1();        // g0 landed (g1 still streaming)
    __syncwarp();
    compute_tile(reinterpret_cast<const ulonglong2*>(wbuf0 + rl * RS + kh * MID),
                 0 * TILE + w * WR);

    // ---- g2: tile1 rows 8-15 -> buf0 rows 0-7 (reuse; WAR-safe in practice) ----
#pragma unroll
    for (int rr = 0; rr < 8; rr++)
        cp16(db0 + rr * (RS * 4) + lo, row_ptr(TILE + w * WR + 8 + rr) + lane * 4);
    CP_COMMIT();

    CP_WAIT0();        // g1 + g2 landed
    __syncwarp();
    {
        // tile 1: rows 0-7 live in buf1, rows 8-15 live in buf0 rows 0-7
        const float* base = (rl < 8) ? (wbuf1 + rl * RS) : (wbuf0 + (rl - 8) * RS);
        compute_tile(reinterpret_cast<const ulonglong2*>(base + kh * MID),
                     1 * TILE + w * WR);
    }
    __syncthreads();   // sdm complete

    // ---- gather positive distances per anchor (atomic append) ----
    {
        int myl = slab[t];
#pragma unroll
        for (int i = 0; i < ANCH; i++) {
            int a = blk * ANCH + i;
            if (myl == slab[a] && t != a) {
                int k = atomicAdd(&snpos[i], 1);
                if (k < PMAX) spp[i][k] = sdm[i * Nd + t];
            }
        }
    }
    __syncthreads();

    // ---- rank-sort positives ascending into srt (INF padded) ----
    if (t < ANCH * PMAX) {
        int i = t >> 6, q = t & 63;
        int P = min(snpos[i], PMAX);
        if (q < P) {
            float v = spp[i][q];
            int rk = 0;
            for (int j = 0; j < P; j++) {
                float u = spp[i][j];
                rk += (u < v) || (u == v && j < q);
            }
            srt[i][rk] = v;
        }
    }
    __syncthreads();

    // ---- suffix sums via reversed warp prefix-scan (warp i -> anchor i) ----
    if (w < ANCH) {
        int P = min(snpos[w], PMAX);
        int j0 = lane, j1 = 32 + lane;
        float x0 = (63 - j0 < P) ? srt[w][63 - j0] : 0.f;
        float x1 = (63 - j1 < P) ? srt[w][63 - j1] : 0.f;
        float s0 = x0, s1 = x1;
#pragma unroll
        for (int o = 1; o < 32; o <<= 1) {
            float v = __shfl_up_sync(0xffffffffu, s0, o);
            if (lane >= o) s0 += v;
        }
        float tot0 = __shfl_sync(0xffffffffu, s0, 31);
#pragma unroll
        for (int o = 1; o < 32; o <<= 1) {
            float v = __shfl_up_sync(0xffffffffu, s1, o);
            if (lane >= o) s1 += v;
        }
        s1 += tot0;
        sfx[w][63 - j0] = s0;   // sfx[k] = sum_{j>=k, j<P} srt[j]
        sfx[w][31 - lane] = s1;
    }
    __syncthreads();

    // ---- triplet reduction: thread t = negative n; binary search per anchor ----
    float        lsum = 0.0f;
    unsigned int lcnt = 0;
    {
        int myl = slab[t];
#pragma unroll
        for (int i = 0; i < ANCH; i++) {
            int a = blk * ANCH + i;
            if (myl != slab[a]) {
                float dan = sdm[i * Nd + t];
                int P = min(snpos[i], PMAX);
                int lo2 = 0;   // count of positives <= dan
#pragma unroll
                for (int s = 32; s > 0; s >>= 1)
                    if (srt[i][lo2 + s - 1] <= dan) lo2 += s;
                int cg = P - lo2;                 // positives with d_ap > d_an
                lsum += sfx[i][lo2] - (float)cg * dan;
                lcnt += (unsigned)cg;
            }
        }
    }

    // ---- block reduce (sum, count) ----
#pragma unroll
    for (int o = 16; o > 0; o >>= 1) {
        lsum += __shfl_xor_sync(0xffffffffu, lsum, o);
        lcnt += __shfl_xor_sync(0xffffffffu, lcnt, o);
    }
    if (lane == 0) { swsum[w] = lsum; swcnt[w] = lcnt; }
    __syncthreads();

    if (t == 0) {
        float bs = 0.0f; unsigned int bc = 0;
#pragma unroll
        for (int k = 0; k < NW; k++) { bs += swsum[k]; bc += swcnt[k]; }
        g_part[blk] = bs;
        g_cntp[blk] = bc;
        __threadfence();
        unsigned int old = atomicAdd(&g_done, 1);
        sIsLast = (old == GRID - 1);
    }
    __syncthreads();

    // ---- last block finalizes (AvgNonZeroReducer) ----
    if (sIsLast) {
        __threadfence();
        float        s = 0.0f;
        unsigned int c = 0;
        if (t < GRID) {
            s = ((volatile float*)g_part)[t];
            c = ((volatile unsigned int*)g_cntp)[t];
        }
#pragma unroll
        for (int o = 16; o > 0; o >>= 1) {
            s += __shfl_xor_sync(0xffffffffu, s, o);
            c += __shfl_xor_sync(0xffffffffu, c, o);
        }
        if (t < GRID && lane == 0) { swsum[w] = s; swcnt[w] = c; }
        __syncthreads();
        if (t == 0) {
            float S = swsum[0] + swsum[1] + swsum[2] + swsum[3];
            unsigned int C = swcnt[0] + swcnt[1] + swcnt[2] + swcnt[3];
            out[0] = (C > 0) ? (S / (float)C) : 0.0f;
            g_done = 0;   // reset for next graph replay
        }
    }
}

extern "C" void kernel_launch(void* const* d_in, const int* in_sizes, int n_in,
                              void* d_out, int out_size) {
    const float* feat   = (const float*)d_in[0];   // [128, 4, 128] float32
    const int*   labels = (const int*)d_in[1];     // [128] int32
    float*       out    = (float*)d_out;           // scalar float32

    cudaFuncSetAttribute(fused_triplet_kernel,
                         cudaFuncAttributeMaxDynamicSharedMemorySize,
                         DYN_BYTES);
    fused_triplet_kernel<<<GRID, NT, DYN_BYTES>>>(feat, labels, out);
}

// round 15
// speedup vs baseline: 1.1382x; 1.1382x over previous
#include <cuda_runtime.h>
#include <math.h>

// Problem constants (fixed by the reference setup)
#define Bd   128
#define Vd   4
#define Dd   128
#define Nd   512           // B*V
#define ANCH 4             // anchors per block
#define GRID (Nd / ANCH)   // 128 blocks
#define NT   512           // threads per block
#define NW   16            // warps
#define TILE 256           // rows per tile
#define NTIL (Nd / TILE)   // 2 tiles
#define RS   132           // padded row stride (conflict-free LDS.128)
#define PRS  5             // partial stride (gcd(5,32)=1)
#define PMAX 64            // max positives per anchor (padded)

#define SM_TILE (TILE * RS)
#define SM_SDM  (ANCH * Nd)
#define SM_SA   (ANCH * Dd)
#define SM_PRT  (TILE * PRS)
#define DYN_BYTES ((SM_TILE + SM_SDM + SM_SA + SM_PRT) * 4)

#define INF_F __int_as_float(0x7f800000)

// Scratch (device globals — no allocation allowed)
__device__ float        g_part[GRID];
__device__ unsigned int g_cntp[GRID];
__device__ unsigned int g_done = 0;

// packed fp32x2 helpers
__device__ __forceinline__ void fma2(unsigned long long& acc,
                                     unsigned long long a,
                                     unsigned long long b) {
    asm("fma.rn.f32x2 %0, %1, %2, %0;" : "+l"(acc) : "l"(a), "l"(b));
}
__device__ __forceinline__ float sum2(unsigned long long v) {
    float lo, hi;
    asm("mov.b64 {%0,%1}, %2;" : "=f"(lo), "=f"(hi) : "l"(v));
    return lo + hi;
}

__global__ void __launch_bounds__(NT, 1)
fused_triplet_kernel(const float* __restrict__ feat,
                     const int*   __restrict__ labels,
                     float*       __restrict__ out) {
    extern __shared__ float smem[];
    float* tile = smem;                 // TILE * RS
    float* sdm  = tile + SM_TILE;       // ANCH * Nd
    float* sa   = sdm + SM_SDM;         // ANCH * Dd
    float* prt  = sa + SM_SA;           // TILE * PRS

    __shared__ int          slab[Nd];
    __shared__ float        spp[ANCH][PMAX];     // positive distances (index order)
    __shared__ float        srt[ANCH][PMAX];     // sorted asc, INF padded
    __shared__ float        sfx[ANCH][PMAX];     // suffix sums
    __shared__ int          wcnt[ANCH][NW];      // per-warp positive counts
    __shared__ int          woff[ANCH][NW];      // exclusive warp offsets
    __shared__ int          snpos[ANCH];
    __shared__ float        s_invna[ANCH];
    __shared__ float        swsum[NW];
    __shared__ unsigned int swcnt[NW];
    __shared__ int          sIsLast;

    const int t    = threadIdx.x;
    const int w    = t >> 5;
    const int lane = t & 31;
    const int blk  = blockIdx.x;

    // row n of emb <- features[n & 127, n >> 7, :]
    auto row_ptr = [&](int n) -> const float* {
        return feat + (size_t)(n & (Bd - 1)) * (Vd * Dd) + (n >> 7) * Dd;
    };

    // ---- stage tile 0: warp w stages rows w*16 .. w*16+15 (coalesced) ----
#pragma unroll
    for (int rr = 0; rr < 16; rr++) {
        int lrow = w * 16 + rr;
        reinterpret_cast<float4*>(tile + lrow * RS)[lane] =
            reinterpret_cast<const float4*>(row_ptr(lrow))[lane];
    }

    slab[t] = labels[t & (Bd - 1)];
    if (t < ANCH * Dd) {
        int i = t >> 7;
        int d = t & (Dd - 1);
        sa[i * Dd + d] = row_ptr(blk * ANCH + i)[d];
    }
    if (t < ANCH * PMAX) srt[t >> 6][t & 63] = INF_F;
    __syncthreads();

    // anchor inverse norms (warps 0..3; consumed after the in-loop barrier)
    if (w < ANCH) {
        float4 v = reinterpret_cast<const float4*>(sa + w * Dd)[lane];
        float s = v.x * v.x + v.y * v.y + v.z * v.z + v.w * v.w;
#pragma unroll
        for (int o = 16; o > 0; o >>= 1) s += __shfl_xor_sync(0xffffffffu, s, o);
        if (lane == 0) s_invna[w] = rsqrtf(s);
    }

    const int r  = t & (TILE - 1);   // row within tile
    const int kh = t >> 8;           // k-half: 0 or 1

    const ulonglong2* a0p = reinterpret_cast<const ulonglong2*>(sa + 0 * Dd + kh * 64);
    const ulonglong2* a1p = reinterpret_cast<const ulonglong2*>(sa + 1 * Dd + kh * 64);
    const ulonglong2* a2p = reinterpret_cast<const ulonglong2*>(sa + 2 * Dd + kh * 64);
    const ulonglong2* a3p = reinterpret_cast<const ulonglong2*>(sa + 3 * Dd + kh * 64);

#pragma unroll
    for (int tt = 0; tt < NTIL; tt++) {
        // ---- compute: thread owns (row r, k-half kh); packed f32x2 FMAs ----
        const ulonglong2* rowp =
            reinterpret_cast<const ulonglong2*>(tile + r * RS + kh * 64);
        unsigned long long c0a=0,c0b=0,c1a=0,c1b=0,c2a=0,c2b=0,
                           c3a=0,c3b=0,c4a=0,c4b=0;
#pragma unroll
        for (int c = 0; c < 16; c++) {
            ulonglong2 f  = rowp[c];
            ulonglong2 a0 = a0p[c];    // warp-uniform -> broadcast
            ulonglong2 a1 = a1p[c];
            ulonglong2 a2 = a2p[c];
            ulonglong2 a3 = a3p[c];
            fma2(c0a, f.x, a0.x);  fma2(c0b, f.y, a0.y);
            fma2(c1a, f.x, a1.x);  fma2(c1b, f.y, a1.y);
            fma2(c2a, f.x, a2.x);  fma2(c2b, f.y, a2.y);
            fma2(c3a, f.x, a3.x);  fma2(c3b, f.y, a3.y);
            fma2(c4a, f.x, f.x);   fma2(c4b, f.y, f.y);
        }
        float d0 = sum2(c0a) + sum2(c0b);
        float d1 = sum2(c1a) + sum2(c1b);
        float d2 = sum2(c2a) + sum2(c2b);
        float d3 = sum2(c3a) + sum2(c3b);
        float sq = sum2(c4a) + sum2(c4b);

        if (kh == 1) {
            float* pp = prt + r * PRS;
            pp[0] = d0; pp[1] = d1; pp[2] = d2; pp[3] = d3; pp[4] = sq;
        }
        __syncthreads();
        if (kh == 0) {
            const float* pp = prt + r * PRS;
            d0 += pp[0]; d1 += pp[1]; d2 += pp[2]; d3 += pp[3]; sq += pp[4];
            float invnj = rsqrtf(sq);
            int gj = tt * TILE + r;
            float s0 = fmaxf(2.f - 2.f * (d0 * s_invna[0] * invnj), 0.f);
            float s1 = fmaxf(2.f - 2.f * (d1 * s_invna[1] * invnj), 0.f);
            float s2 = fmaxf(2.f - 2.f * (d2 * s_invna[2] * invnj), 0.f);
            float s3 = fmaxf(2.f - 2.f * (d3 * s_invna[3] * invnj), 0.f);
            sdm[0 * Nd + gj] = (s0 > 0.f) ? s0 * rsqrtf(s0) : 0.f;
            sdm[1 * Nd + gj] = (s1 > 0.f) ? s1 * rsqrtf(s1) : 0.f;
            sdm[2 * Nd + gj] = (s2 > 0.f) ? s2 * rsqrtf(s2) : 0.f;
            sdm[3 * Nd + gj] = (s3 > 0.f) ? s3 * rsqrtf(s3) : 0.f;
        }
        // stage the next tile (tile fully consumed before the mid-barrier)
        if (tt + 1 < NTIL) {
#pragma unroll
            for (int rr = 0; rr < 16; rr++) {
                int lrow = w * 16 + rr;
                reinterpret_cast<float4*>(tile + lrow * RS)[lane] =
                    reinterpret_cast<const float4*>(
                        row_ptr((tt + 1) * TILE + lrow))[lane];
            }
        }
        __syncthreads();
    }

    // ---- ballot-based positive gather (no shared atomics) ----
    const int myl = slab[t];
    unsigned lml = (1u << lane) - 1u;
    bool isp[ANCH]; int inw[ANCH];
#pragma unroll
    for (int i = 0; i < ANCH; i++) {
        int a  = blk * ANCH + i;
        int la = slab[a];
        isp[i] = (myl == la) && (t != a);
        unsigned bal = __ballot_sync(0xffffffffu, isp[i]);
        inw[i] = __popc(bal & lml);
        if (lane == 0) wcnt[i][w] = __popc(bal);
    }
    __syncthreads();
    if (w < ANCH) {    // warp i scans its 16 warp-counts
        int c = (lane < NW) ? wcnt[w][lane] : 0;
        int s = c;
#pragma unroll
        for (int o = 1; o < NW; o <<= 1) {
            int v = __shfl_up_sync(0xffffffffu, s, o);
            if (lane >= o) s += v;
        }
        if (lane < NW) woff[w][lane] = s - c;   // exclusive
        if (lane == NW - 1) snpos[w] = s;       // total
    }
    __syncthreads();
#pragma unroll
    for (int i = 0; i < ANCH; i++) {
        if (isp[i]) {
            int idx = woff[i][w] + inw[i];
            if (idx < PMAX) spp[i][idx] = sdm[i * Nd + t];
        }
    }
    __syncthreads();

    // ---- rank-sort positives ascending into srt (INF padded) ----
    if (t < ANCH * PMAX) {
        int i = t >> 6, q = t & 63;
        int P = min(snpos[i], PMAX);
        if (q < P) {
            float v = spp[i][q];
            int rk = 0;
            for (int j = 0; j < P; j++) {
                float u = spp[i][j];
                rk += (u < v) || (u == v && j < q);
            }
            srt[i][rk] = v;
        }
    }
    __syncthreads();

    // ---- suffix sums via reversed warp prefix-scan (warp i -> anchor i) ----
    if (w < ANCH) {
        int P = min(snpos[w], PMAX);
        int j0 = lane, j1 = 32 + lane;
        float x0 = (63 - j0 < P) ? srt[w][63 - j0] : 0.f;
        float x1 = (63 - j1 < P) ? srt[w][63 - j1] : 0.f;
        float s0 = x0, s1 = x1;
#pragma unroll
        for (int o = 1; o < 32; o <<= 1) {
            float v = __shfl_up_sync(0xffffffffu, s0, o);
            if (lane >= o) s0 += v;
        }
        float tot0 = __shfl_sync(0xffffffffu, s0, 31);
#pragma unroll
        for (int o = 1; o < 32; o <<= 1) {
            float v = __shfl_up_sync(0xffffffffu, s1, o);
            if (lane >= o) s1 += v;
        }
        s1 += tot0;
        sfx[w][63 - j0] = s0;   // sfx[k] = sum_{j>=k, j<P} srt[j]
        sfx[w][31 - lane] = s1;
    }
    __syncthreads();

    // ---- triplet reduction: branchless, 4 interleaved binary searches ----
    float        lsum = 0.0f;
    unsigned int lcnt = 0;
    {
        float dan[ANCH]; int lo[ANCH];
#pragma unroll
        for (int i = 0; i < ANCH; i++) { dan[i] = sdm[i * Nd + t]; lo[i] = 0; }
#pragma unroll
        for (int s = 32; s > 0; s >>= 1) {
#pragma unroll
            for (int i = 0; i < ANCH; i++)
                if (srt[i][lo[i] + s - 1] <= dan[i]) lo[i] += s;
        }
#pragma unroll
        for (int i = 0; i < ANCH; i++) {
            int a = blk * ANCH + i;
            bool valid = (myl != slab[a]);
            int cg = snpos[i] - lo[i];            // positives with d_ap > d_an
            float contrib = sfx[i][lo[i]] - (float)cg * dan[i];
            lsum += valid ? contrib : 0.0f;
            lcnt += valid ? (unsigned)cg : 0u;
        }
    }

    // ---- block reduce (sum, count) ----
#pragma unroll
    for (int o = 16; o > 0; o >>= 1) {
        lsum += __shfl_xor_sync(0xffffffffu, lsum, o);
        lcnt += __shfl_xor_sync(0xffffffffu, lcnt, o);
    }
    if (lane == 0) { swsum[w] = lsum; swcnt[w] = lcnt; }
    __syncthreads();

    if (t == 0) {
        float bs = 0.0f; unsigned int bc = 0;
#pragma unroll
        for (int k = 0; k < NW; k++) { bs += swsum[k]; bc += swcnt[k]; }
        g_part[blk] = bs;
        g_cntp[blk] = bc;
        __threadfence();
        unsigned int old = atomicAdd(&g_done, 1);
        sIsLast = (old == GRID - 1);
    }
    __syncthreads();

    // ---- last block finalizes (AvgNonZeroReducer) ----
    if (sIsLast) {
        __threadfence();
        float        s = 0.0f;
        unsigned int c = 0;
        if (t < GRID) {
            s = ((volatile float*)g_part)[t];
            c = ((volatile unsigned int*)g_cntp)[t];
        }
#pragma unroll
        for (int o = 16; o > 0; o >>= 1) {
            s += __shfl_xor_sync(0xffffffffu, s, o);
            c += __shfl_xor_sync(0xffffffffu, c, o);
        }
        if (t < GRID && lane == 0) { swsum[w] = s; swcnt[w] = c; }
        __syncthreads();
        if (t == 0) {
            float S = swsum[0] + swsum[1] + swsum[2] + swsum[3];
            unsigned int C = swcnt[0] + swcnt[1] + swcnt[2] + swcnt[3];
            out[0] = (C > 0) ? (S / (float)C) : 0.0f;
            g_done = 0;   // reset for next graph replay
        }
    }
}

extern "C" void kernel_launch(void* const* d_in, const int* in_sizes, int n_in,
                              void* d_out, int out_size) {
    const float* feat   = (const float*)d_in[0];   // [128, 4, 128] float32
    const int*   labels = (const int*)d_in[1];     // [128] int32
    float*       out    = (float*)d_out;           // scalar float32

    cudaFuncSetAttribute(fused_triplet_kernel,
                         cudaFuncAttributeMaxDynamicSharedMemorySize,
                         DYN_BYTES);
    fused_triplet_kernel<<<GRID, NT, DYN_BYTES>>>(feat, labels, out);
}